// round 16
// baseline (speedup 1.0000x reference)
#include <cuda_runtime.h>
#include <cuda_bf16.h>
#include <stdint.h>

#define BB 2
#define SS 2048
#define DD 1024
#define HH 16
#define DHD 64
#define MM (BB*SS)      // 4096
#define NHEAD (BB*HH)   // 32

typedef __nv_bfloat16 bf16;

// ---------------------------------------------------------------------------
// Globals: EXACTLY 64MB (the empirically safe budget: every passing round had
// exactly this; >64MB tripped the 128MiB guard in R6/R15).
// XH/XL hold split(x) for qkv, then attn overwrites them with split(att).
// ---------------------------------------------------------------------------
#define DEVARR __device__ __align__(16)
DEVARR bf16 XH [(size_t)MM*DD];        DEVARR bf16 XL [(size_t)MM*DD];
DEVARR bf16 QHg[(size_t)NHEAD*SS*DHD]; DEVARR bf16 QLg[(size_t)NHEAD*SS*DHD];
DEVARR bf16 KHg[(size_t)NHEAD*SS*DHD]; DEVARR bf16 KLg[(size_t)NHEAD*SS*DHD];
DEVARR bf16 VHg[(size_t)NHEAD*SS*DHD]; DEVARR bf16 VLg[(size_t)NHEAD*SS*DHD];

// ---------------------------------------------------------------------------
// Fast packed split: bit-identical to the old per-element rn split
// (identical roundings), ~half the instructions.
// hi = {bf16(x1) : bf16(x0)}, lo = {bf16(x1-h1) : bf16(x0-h0)}
// ---------------------------------------------------------------------------
__device__ __forceinline__ void split_pair(float x0, float x1, uint32_t& hi, uint32_t& lo) {
    uint32_t h;
    asm("cvt.rn.bf16x2.f32 %0, %1, %2;" : "=r"(h) : "f"(x1), "f"(x0));
    const float h0 = __uint_as_float(h << 16);
    const float h1 = __uint_as_float(h & 0xFFFF0000u);
    uint32_t l;
    asm("cvt.rn.bf16x2.f32 %0, %1, %2;" : "=r"(l) : "f"(x1 - h1), "f"(x0 - h0));
    hi = h; lo = l;
}
__device__ __forceinline__ void mma16(float* d, const uint32_t* a, uint32_t b0, uint32_t b1) {
    asm volatile("mma.sync.aligned.m16n8k16.row.col.f32.bf16.bf16.f32 "
        "{%0,%1,%2,%3}, {%4,%5,%6,%7}, {%8,%9}, {%0,%1,%2,%3};"
        : "+f"(d[0]), "+f"(d[1]), "+f"(d[2]), "+f"(d[3])
        : "r"(a[0]), "r"(a[1]), "r"(a[2]), "r"(a[3]), "r"(b0), "r"(b1));
}

// A-frag layout, m128: [split][kb][wb(8)][lane][reg]  (8192 words, 32KB)
#define AFI8(s,kb,wb,l,r) (((((s)*2+(kb))*8+(wb))*32+(l))*4+(r))
// B-frag layout, n64: [split][kb][lane][idx 0..15], stride 20 (2560 words, 10KB)
#define BFI(s,kb,l,i)     ((((s)*2+(kb))*32+(l))*20+(i))

// ---------------------------------------------------------------------------
// prep: split x into hi/lo planes (one time)
// ---------------------------------------------------------------------------
__global__ __launch_bounds__(256) void splitx_kernel(const float* __restrict__ src) {
    const size_t i = ((size_t)blockIdx.x * 256 + threadIdx.x) * 4;
    const float4 v = *(const float4*)&src[i];
    uint32_t h0, l0, h1, l1;
    split_pair(v.x, v.y, h0, l0);
    split_pair(v.z, v.w, h1, l1);
    *(uint2*)&XH[i] = make_uint2(h0, h1);
    *(uint2*)&XL[i] = make_uint2(l0, l1);
}

// staging helpers (BM=128, BK=32)
// A: 8 u32 per plane per thread (row arow, k-half ahk), scatter to frag order
__device__ __forceinline__ void storeA_128(uint32_t* smA,
    uint4 p0, uint4 p1, uint4 q0, uint4 q1, int ahk, int wb, int ag, int arh)
{
    uint32_t uh[8], ul[8];
    *(uint4*)&uh[0] = p0;  *(uint4*)&uh[4] = p1;
    *(uint4*)&ul[0] = q0;  *(uint4*)&ul[4] = q1;
    #pragma unroll
    for (int p = 0; p < 8; p++) {
        const int reg = arh + 2*(p >> 2);
        const int ln  = ag*4 + (p & 3);
        smA[AFI8(0,ahk,wb,ln,reg)] = uh[p];
        smA[AFI8(1,ahk,wb,ln,reg)] = ul[p];
    }
}
// B: 2 k-rows x 4 n-cols per thread, split + scatter
__device__ __forceinline__ void storeB_64n(uint32_t* smB,
    float4 r0, float4 r1, int n4, int kbB, int regB, int tB)
{
    const float w0[4] = {r0.x, r0.y, r0.z, r0.w};
    const float w1[4] = {r1.x, r1.y, r1.z, r1.w};
    #pragma unroll
    for (int j = 0; j < 4; j++) {
        const int n = n4 + j, gn = n & 7, nt = n >> 3;
        uint32_t hh, ll;
        split_pair(w0[j], w1[j], hh, ll);
        smB[BFI(0,kbB, gn*4+tB, nt*2+regB)] = hh;
        smB[BFI(1,kbB, gn*4+tB, nt*2+regB)] = ll;
    }
}

// ---------------------------------------------------------------------------
// GEMM mainloop: C[m128 x n64] = Asplit[m128 x 1024] @ B[1024 x n64], BK=32.
// 256 thr, 8 warps: warp = m32 x n32 (wms = warp>>1, wnh = warp&1).
// LDS/MMA = 0.33 (B-fragments reused across 2 m-fragments). 2 blocks/SM.
// Per iter: [LDG next -> regs] [96 MMAs/warp] sync [STS next] sync. 32 iters.
// ---------------------------------------------------------------------------
#define GEMM_BODY5(A_H, A_L, BROW_STRIDE, WSRC)                                     \
    __shared__ uint32_t smA[8192];                                                  \
    __shared__ uint32_t smB[2560];                                                  \
    const int tid  = threadIdx.x;                                                   \
    const int lane = tid & 31, warp = tid >> 5;                                     \
    const int arow = tid >> 1, ahk = tid & 1;                                       \
    const int awb = arow >> 4, ag = arow & 7, arh = (arow >> 3) & 1;                \
    const int kp = tid >> 4, n4 = (tid & 15) * 4;                                   \
    const int kbB = kp >> 3, regB = (kp >> 2) & 1, tB = kp & 3;                     \
    const int wms = warp >> 1, wnh = warp & 1;                                      \
    const uint32_t* xh = (const uint32_t*)(A_H) + (size_t)arow*(DD/2) + ahk*8;      \
    const uint32_t* xl = (const uint32_t*)(A_L) + (size_t)arow*(DD/2) + ahk*8;      \
    float acc[8][4] = {};                                                           \
    uint4 pa0, pa1, pl0, pl1;                                                       \
    float4 wv0, wv1;                                                                \
    pa0 = *(const uint4*)&xh[0];  pa1 = *(const uint4*)&xh[4];                      \
    pl0 = *(const uint4*)&xl[0];  pl1 = *(const uint4*)&xl[4];                      \
    {   const float* wr = WSRC + (size_t)(2*kp) * (BROW_STRIDE);                    \
        wv0 = *(const float4*)&wr[0];                                               \
        wv1 = *(const float4*)&wr[BROW_STRIDE]; }                                   \
    storeA_128(smA, pa0, pa1, pl0, pl1, ahk, awb, ag, arh);                         \
    storeB_64n(smB, wv0, wv1, n4, kbB, regB, tB);                                   \
    __syncthreads();                                                                \
    for (int it = 0; it < 32; it++) {                                               \
        const bool more = (it + 1 < 32);                                            \
        if (more) {                                                                 \
            const int w = (it+1)*16;                                                \
            pa0 = *(const uint4*)&xh[w];  pa1 = *(const uint4*)&xh[w+4];            \
            pl0 = *(const uint4*)&xl[w];  pl1 = *(const uint4*)&xl[w+4];            \
            const float* wr = WSRC + (size_t)((it+1)*32 + 2*kp) * (BROW_STRIDE);    \
            wv0 = *(const float4*)&wr[0];                                           \
            wv1 = *(const float4*)&wr[BROW_STRIDE];                                 \
        }                                                                           \
        _Pragma("unroll")                                                           \
        for (int kb = 0; kb < 2; kb++) {                                            \
            uint32_t AH0[4], AL0[4], AH1[4], AL1[4];                                \
            *(uint4*)AH0 = *(const uint4*)&smA[AFI8(0,kb,2*wms,  lane,0)];          \
            *(uint4*)AL0 = *(const uint4*)&smA[AFI8(1,kb,2*wms,  lane,0)];          \
            *(uint4*)AH1 = *(const uint4*)&smA[AFI8(0,kb,2*wms+1,lane,0)];          \
            *(uint4*)AL1 = *(const uint4*)&smA[AFI8(1,kb,2*wms+1,lane,0)];          \
            _Pragma("unroll")                                                       \
            for (int ql = 0; ql < 2; ql++) {                                        \
                const int bix = wnh*8 + 4*ql;                                       \
                const uint4 h4 = *(const uint4*)&smB[BFI(0,kb,lane,bix)];           \
                const uint4 l4 = *(const uint4*)&smB[BFI(1,kb,lane,bix)];           \
                float* a00 = acc[0*4 + ql*2 + 0];                                   \
                float* a01 = acc[0*4 + ql*2 + 1];                                   \
                float* a10 = acc[1*4 + ql*2 + 0];                                   \
                float* a11 = acc[1*4 + ql*2 + 1];                                   \
                mma16(a00, AH0, h4.x, h4.y);  mma16(a01, AH0, h4.z, h4.w);          \
                mma16(a10, AH1, h4.x, h4.y);  mma16(a11, AH1, h4.z, h4.w);          \
                mma16(a00, AH0, l4.x, l4.y);  mma16(a01, AH0, l4.z, l4.w);          \
                mma16(a10, AH1, l4.x, l4.y);  mma16(a11, AH1, l4.z, l4.w);          \
                mma16(a00, AL0, h4.x, h4.y);  mma16(a01, AL0, h4.z, h4.w);          \
                mma16(a10, AL1, h4.x, h4.y);  mma16(a11, AL1, h4.z, h4.w);          \
            }                                                                       \
        }                                                                           \
        __syncthreads();                                                            \
        if (more) {                                                                 \
            storeA_128(smA, pa0, pa1, pl0, pl1, ahk, awb, ag, arh);                 \
            storeB_64n(smB, wv0, wv1, n4, kbB, regB, tB);                           \
        }                                                                           \
        __syncthreads();                                                            \
    }

// ---------------------------------------------------------------------------
// Kernel 1: fused QKV projection. BM=128, n64 (one head/block).
// grid (32, 48): y -> which = y/16, head = y%16. 256 thr.
// ---------------------------------------------------------------------------
__global__ __launch_bounds__(256) void qkv_kernel(
    const float* __restrict__ Wq, const float* __restrict__ Wk, const float* __restrict__ Wv,
    const float* __restrict__ bq, const float* __restrict__ bk, const float* __restrict__ bv)
{
    const int m0 = blockIdx.x * 128;
    const int which = blockIdx.y >> 4, h = blockIdx.y & 15;
    const float* Wb = (which == 0) ? Wq : (which == 1) ? Wk : Wv;
    const float* wsrc = Wb + (size_t)h * DD * DHD + (threadIdx.x & 15) * 4;

    GEMM_BODY5(XH + (size_t)m0 * DD, XL + (size_t)m0 * DD, DHD, wsrc)

    // epilogue: bias, scale(q), split, store planes
    const float* biasb = (which == 0) ? bq : (which == 1) ? bk : bv;
    bf16* oh = (which == 0) ? QHg : (which == 1) ? KHg : VHg;
    bf16* ol = (which == 0) ? QLg : (which == 1) ? KLg : VLg;
    const float sc = (which == 0) ? 0.125f : 1.0f;

    const int g = lane >> 2, t4 = lane & 3;
    #pragma unroll
    for (int mf = 0; mf < 2; mf++)
        #pragma unroll
        for (int ql = 0; ql < 2; ql++)
            #pragma unroll
            for (int nt = 0; nt < 2; nt++) {
                const float* a = acc[mf*4 + ql*2 + nt];
                const int n64 = wnh*32 + ql*16 + nt*8 + 2*t4;
                const float b0 = biasb[h*DHD + n64], b1 = biasb[h*DHD + n64 + 1];
                uint32_t hi, lo;
                int m = m0 + wms*32 + mf*16 + g;
                size_t ridx = (((size_t)(m >> 11) * HH + h) * SS + (m & (SS-1))) * DHD + n64;
                split_pair((a[0] + b0) * sc, (a[1] + b1) * sc, hi, lo);
                *(uint32_t*)&oh[ridx] = hi; *(uint32_t*)&ol[ridx] = lo;
                m += 8;
                ridx = (((size_t)(m >> 11) * HH + h) * SS + (m & (SS-1))) * DHD + n64;
                split_pair((a[2] + b0) * sc, (a[3] + b1) * sc, hi, lo);
                *(uint32_t*)&oh[ridx] = hi; *(uint32_t*)&ol[ridx] = lo;
            }
}

// ---------------------------------------------------------------------------
// Kernel 3: output projection. BM=128, n64/block. grid (32, 16), 256 thr.
// ---------------------------------------------------------------------------
__global__ __launch_bounds__(256) void out_kernel(
    const float* __restrict__ Wo, const float* __restrict__ bo, float* __restrict__ out)
{
    const int m0 = blockIdx.x * 128;
    const int n0 = blockIdx.y * 64;
    const float* wsrc = Wo + n0 + (threadIdx.x & 15) * 4;

    GEMM_BODY5(XH + (size_t)m0 * DD, XL + (size_t)m0 * DD, DD, wsrc)

    const int g = lane >> 2, t4 = lane & 3;
    #pragma unroll
    for (int mf = 0; mf < 2; mf++)
        #pragma unroll
        for (int ql = 0; ql < 2; ql++)
            #pragma unroll
            for (int nt = 0; nt < 2; nt++) {
                const float* a = acc[mf*4 + ql*2 + nt];
                const int n = n0 + wnh*32 + ql*16 + nt*8 + 2*t4;
                const float b0 = bo[n], b1 = bo[n+1];
                const int m_a = m0 + wms*32 + mf*16 + g, m_b = m_a + 8;
                *(float2*)&out[(size_t)m_a * DD + n] = make_float2(a[0] + b0, a[1] + b1);
                *(float2*)&out[(size_t)m_b * DD + n] = make_float2(a[2] + b0, a[3] + b1);
            }
}

// ---------------------------------------------------------------------------
// Kernel 2: flash attention (R9 VERBATIM structure — measured ~51% tensor;
// only split_pair is the faster bit-identical version).
// grid (16, 16, 2), 256 thr, dyn smem 73728 B.
// ---------------------------------------------------------------------------
#define QFI(s,kb,wb,l,r) (((((s)*4+(kb))*8+(wb))*32+(l))*4+(r))   // 8192 words
#define KFI(s,kb,l,i)    ((((s)*4+(kb))*32+(l))*20+(i))           // 5120 words
#define ATT_SMEM_BYTES ((8192 + 5120 + 5120) * 4)

__global__ __launch_bounds__(256) void attn_kernel()
{
    extern __shared__ uint32_t sm[];
    uint32_t* QF = sm;
    uint32_t* KF = sm + 8192;
    uint32_t* VF = sm + 13312;

    const int tid  = threadIdx.x;
    const int lane = tid & 31, warp = tid >> 5;
    const int g = lane >> 2, t4 = lane & 3;
    const int q0 = blockIdx.x * 128;
    const int head = blockIdx.z * HH + blockIdx.y;
    const size_t hb = (size_t)head * SS;

    const int key = tid >> 2, kbK = tid & 3;
    const int gK = key & 7, ntK = key >> 3;
    const int kpV = tid >> 3, d8 = (tid & 7) * 8;
    const int kbV = kpV >> 3, regV = (kpV >> 2) & 1, tV = kpV & 3, ntV = tid & 7;

    const uint32_t* khw = (const uint32_t*)(KHg + (hb + key) * DHD) + kbK*8;
    const uint32_t* klw = (const uint32_t*)(KLg + (hb + key) * DHD) + kbK*8;
    const uint32_t* v0h = (const uint32_t*)(VHg + (hb + 2*kpV    ) * DHD) + d8/2;
    const uint32_t* v1h = (const uint32_t*)(VHg + (hb + 2*kpV + 1) * DHD) + d8/2;
    const uint32_t* v0l = (const uint32_t*)(VLg + (hb + 2*kpV    ) * DHD) + d8/2;
    const uint32_t* v1l = (const uint32_t*)(VLg + (hb + 2*kpV + 1) * DHD) + d8/2;
    const size_t krow = (size_t)64 * DHD / 2;

    uint32_t kuh[8], kul[8], va0[4], va1[4], vb0[4], vb1[4];

    {   // stage Q once
        const int r = tid >> 1, dseg = (tid & 1) * 32;
        const int wb = r >> 4, gg = r & 7, rh = (r >> 3) & 1;
        const uint32_t* qhw = (const uint32_t*)(QHg + (hb + q0 + r) * DHD) + dseg/2;
        const uint32_t* qlw = (const uint32_t*)(QLg + (hb + q0 + r) * DHD) + dseg/2;
        uint32_t uh[16], ul[16];
        #pragma unroll
        for (int c = 0; c < 4; c++) {
            *(uint4*)&uh[c*4] = *(const uint4*)&qhw[c*4];
            *(uint4*)&ul[c*4] = *(const uint4*)&qlw[c*4];
        }
        #pragma unroll
        for (int c4 = 0; c4 < 8; c4++) {
            const int d0 = dseg + c4*4;
            const int kb = d0 >> 4, cc = d0 & 15;
            const int reg = rh + 2*(cc >> 3), ln = gg*4 + ((cc & 7) >> 1);
            QF[QFI(0,kb,wb,ln,  reg)] = uh[c4*2];
            QF[QFI(0,kb,wb,ln+1,reg)] = uh[c4*2+1];
            QF[QFI(1,kb,wb,ln,  reg)] = ul[c4*2];
            QF[QFI(1,kb,wb,ln+1,reg)] = ul[c4*2+1];
        }
    }
    {   // stage KV tile 0
        *(uint4*)&kuh[0] = *(const uint4*)&khw[0];  *(uint4*)&kuh[4] = *(const uint4*)&khw[4];
        *(uint4*)&kul[0] = *(const uint4*)&klw[0];  *(uint4*)&kul[4] = *(const uint4*)&klw[4];
        *(uint4*)va0 = *(const uint4*)v0h;  *(uint4*)va1 = *(const uint4*)v1h;
        *(uint4*)vb0 = *(const uint4*)v0l;  *(uint4*)vb1 = *(const uint4*)v1l;
        #pragma unroll
        for (int c4 = 0; c4 < 4; c4++) {
            const int cc = c4*4, reg = cc >> 3, t0 = (cc & 7) >> 1;
            KF[KFI(0,kbK,gK*4+t0,  ntK*2+reg)] = kuh[c4*2];
            KF[KFI(0,kbK,gK*4+t0+1,ntK*2+reg)] = kuh[c4*2+1];
            KF[KFI(1,kbK,gK*4+t0,  ntK*2+reg)] = kul[c4*2];
            KF[KFI(1,kbK,gK*4+t0+1,ntK*2+reg)] = kul[c4*2+1];
        }
        #pragma unroll
        for (int j = 0; j < 8; j++) {
            const uint32_t sel = (j & 1) ? 0x7632u : 0x5410u;
            VF[KFI(0,kbV, j*4+tV, ntV*2+regV)] = __byte_perm(va0[j>>1], va1[j>>1], sel);
            VF[KFI(1,kbV, j*4+tV, ntV*2+regV)] = __byte_perm(vb0[j>>1], vb1[j>>1], sel);
        }
    }
    __syncthreads();

    float O[8][4] = {};
    float mx0 = -1e30f, mx1 = -1e30f, l0s = 0.f, l1s = 0.f;

    for (int kt = 0; kt < 32; kt++) {
        const bool more = (kt + 1 < 32);
        if (more) {
            const size_t off = (size_t)(kt+1) * krow;
            *(uint4*)&kuh[0] = *(const uint4*)&khw[off];  *(uint4*)&kuh[4] = *(const uint4*)&khw[off+4];
            *(uint4*)&kul[0] = *(const uint4*)&klw[off];  *(uint4*)&kul[4] = *(const uint4*)&klw[off+4];
            *(uint4*)va0 = *(const uint4*)&v0h[off];  *(uint4*)va1 = *(const uint4*)&v1h[off];
            *(uint4*)vb0 = *(const uint4*)&v0l[off];  *(uint4*)vb1 = *(const uint4*)&v1l[off];
        }

        float S[8][4] = {};
        #pragma unroll
        for (int kb = 0; kb < 4; kb++) {
            uint32_t QH[4], QL[4], kh[16], kl[16];
            *(uint4*)QH = *(const uint4*)&QF[QFI(0,kb,warp,lane,0)];
            *(uint4*)QL = *(const uint4*)&QF[QFI(1,kb,warp,lane,0)];
            #pragma unroll
            for (int q = 0; q < 4; q++) {
                *(uint4*)&kh[q*4] = *(const uint4*)&KF[KFI(0,kb,lane,q*4)];
                *(uint4*)&kl[q*4] = *(const uint4*)&KF[KFI(1,kb,lane,q*4)];
            }
            #pragma unroll
            for (int nt = 0; nt < 8; nt++) {
                mma16(S[nt], QH, kh[nt*2], kh[nt*2+1]);
                mma16(S[nt], QH, kl[nt*2], kl[nt*2+1]);
                mma16(S[nt], QL, kh[nt*2], kh[nt*2+1]);
            }
        }

        float mt0 = -1e30f, mt1 = -1e30f;
        #pragma unroll
        for (int nt = 0; nt < 8; nt++) {
            mt0 = fmaxf(mt0, fmaxf(S[nt][0], S[nt][1]));
            mt1 = fmaxf(mt1, fmaxf(S[nt][2], S[nt][3]));
        }
        #pragma unroll
        for (int off = 2; off >= 1; off >>= 1) {
            mt0 = fmaxf(mt0, __shfl_xor_sync(0xffffffffu, mt0, off));
            mt1 = fmaxf(mt1, __shfl_xor_sync(0xffffffffu, mt1, off));
        }
        const float mn0 = fmaxf(mx0, mt0), mn1 = fmaxf(mx1, mt1);
        const float c0 = __expf(mx0 - mn0), c1 = __expf(mx1 - mn1);
        float ls0 = 0.f, ls1 = 0.f;
        #pragma unroll
        for (int nt = 0; nt < 8; nt++) {
            S[nt][0] = __expf(S[nt][0] - mn0); ls0 += S[nt][0];
            S[nt][1] = __expf(S[nt][1] - mn0); ls0 += S[nt][1];
            S[nt][2] = __expf(S[nt][2] - mn1); ls1 += S[nt][2];
            S[nt][3] = __expf(S[nt][3] - mn1); ls1 += S[nt][3];
        }
        #pragma unroll
        for (int off = 2; off >= 1; off >>= 1) {
            ls0 += __shfl_xor_sync(0xffffffffu, ls0, off);
            ls1 += __shfl_xor_sync(0xffffffffu, ls1, off);
        }
        l0s = l0s * c0 + ls0;  l1s = l1s * c1 + ls1;
        mx0 = mn0;             mx1 = mn1;
        #pragma unroll
        for (int nt = 0; nt < 8; nt++) {
            O[nt][0] *= c0; O[nt][1] *= c0;
            O[nt][2] *= c1; O[nt][3] *= c1;
        }

        #pragma unroll
        for (int kb = 0; kb < 4; kb++) {
            uint32_t ph[4], pl[4], vh[16], vl[16];
            split_pair(S[2*kb  ][0], S[2*kb  ][1], ph[0], pl[0]);
            split_pair(S[2*kb  ][2], S[2*kb  ][3], ph[1], pl[1]);
            split_pair(S[2*kb+1][0], S[2*kb+1][1], ph[2], pl[2]);
            split_pair(S[2*kb+1][2], S[2*kb+1][3], ph[3], pl[3]);
            #pragma unroll
            for (int q = 0; q < 4; q++) {
                *(uint4*)&vh[q*4] = *(const uint4*)&VF[KFI(0,kb,lane,q*4)];
                *(uint4*)&vl[q*4] = *(const uint4*)&VF[KFI(1,kb,lane,q*4)];
            }
            #pragma unroll
            for (int nt = 0; nt < 8; nt++) {
                mma16(O[nt], ph, vh[nt*2], vh[nt*2+1]);
                mma16(O[nt], ph, vl[nt*2], vl[nt*2+1]);
                mma16(O[nt], pl, vh[nt*2], vh[nt*2+1]);
            }
        }
        __syncthreads();
        if (more) {
            #pragma unroll
            for (int c4 = 0; c4 < 4; c4++) {
                const int cc = c4*4, reg = cc >> 3, t0 = (cc & 7) >> 1;
                KF[KFI(0,kbK,gK*4+t0,  ntK*2+reg)] = kuh[c4*2];
                KF[KFI(0,kbK,gK*4+t0+1,ntK*2+reg)] = kuh[c4*2+1];
                KF[KFI(1,kbK,gK*4+t0,  ntK*2+reg)] = kul[c4*2];
                KF[KFI(1,kbK,gK*4+t0+1,ntK*2+reg)] = kul[c4*2+1];
            }
            #pragma unroll
            for (int j = 0; j < 8; j++) {
                const uint32_t sel = (j & 1) ? 0x7632u : 0x5410u;
                VF[KFI(0,kbV, j*4+tV, ntV*2+regV)] = __byte_perm(va0[j>>1], va1[j>>1], sel);
                VF[KFI(1,kbV, j*4+tV, ntV*2+regV)] = __byte_perm(vb0[j>>1], vb1[j>>1], sel);
            }
        }
        __syncthreads();
    }

    const float i0 = 1.f / l0s, i1 = 1.f / l1s;
    #pragma unroll
    for (int nt = 0; nt < 8; nt++) {
        const int n = nt*8 + 2*t4;
        const int sa = q0 + warp*16 + g, sb = sa + 8;
        const size_t ia = ((size_t)blockIdx.z * SS + sa) * DD + blockIdx.y * DHD + n;
        const size_t ib = ((size_t)blockIdx.z * SS + sb) * DD + blockIdx.y * DHD + n;
        uint32_t hi, lo;
        split_pair(O[nt][0]*i0, O[nt][1]*i0, hi, lo);
        *(uint32_t*)&XH[ia] = hi; *(uint32_t*)&XL[ia] = lo;
        split_pair(O[nt][2]*i1, O[nt][3]*i1, hi, lo);
        *(uint32_t*)&XH[ib] = hi; *(uint32_t*)&XL[ib] = lo;
    }
}

// ---------------------------------------------------------------------------
extern "C" void kernel_launch(void* const* d_in, const int* in_sizes, int n_in,
                              void* d_out, int out_size)
{
    (void)in_sizes; (void)n_in; (void)out_size;
    const float* x  = (const float*)d_in[0];
    const float* Wq = (const float*)d_in[1];
    const float* Wk = (const float*)d_in[2];
    const float* Wv = (const float*)d_in[3];
    const float* bq = (const float*)d_in[4];
    const float* bk = (const float*)d_in[5];
    const float* bv = (const float*)d_in[6];
    const float* Wo = (const float*)d_in[7];
    const float* bo = (const float*)d_in[8];
    float* out = (float*)d_out;

    (void)cudaFuncSetAttribute(attn_kernel, cudaFuncAttributeMaxDynamicSharedMemorySize,
                               ATT_SMEM_BYTES);

    splitx_kernel<<<(MM*DD)/1024, 256>>>(x);
    qkv_kernel<<<dim3(MM/128, 48), 256>>>(Wq, Wk, Wv, bq, bk, bv);
    attn_kernel<<<dim3(SS/128, HH, BB), 256, ATT_SMEM_BYTES>>>();
    out_kernel<<<dim3(MM/128, DD/64), 256>>>(Wo, bo, out);
}

// round 17
// speedup vs baseline: 1.1641x; 1.1641x over previous
#include <cuda_runtime.h>
#include <cuda_bf16.h>
#include <stdint.h>

#define BB 2
#define SS 2048
#define DD 1024
#define HH 16
#define DHD 64
#define MM (BB*SS)      // 4096
#define NHEAD (BB*HH)   // 32

typedef __nv_bfloat16 bf16;

// ---------------------------------------------------------------------------
// Globals: EXACTLY 64MB (the empirically safe budget).
// XH/XL hold split(x) for qkv, then attn overwrites them with split(att).
// ---------------------------------------------------------------------------
#define DEVARR __device__ __align__(16)
DEVARR bf16 XH [(size_t)MM*DD];        DEVARR bf16 XL [(size_t)MM*DD];
DEVARR bf16 QHg[(size_t)NHEAD*SS*DHD]; DEVARR bf16 QLg[(size_t)NHEAD*SS*DHD];
DEVARR bf16 KHg[(size_t)NHEAD*SS*DHD]; DEVARR bf16 KLg[(size_t)NHEAD*SS*DHD];
DEVARR bf16 VHg[(size_t)NHEAD*SS*DHD]; DEVARR bf16 VLg[(size_t)NHEAD*SS*DHD];

// ---------------------------------------------------------------------------
// Fast packed split (verified bit-identical in R16): ~half the instructions.
// ---------------------------------------------------------------------------
__device__ __forceinline__ void split_pair(float x0, float x1, uint32_t& hi, uint32_t& lo) {
    uint32_t h;
    asm("cvt.rn.bf16x2.f32 %0, %1, %2;" : "=r"(h) : "f"(x1), "f"(x0));
    const float h0 = __uint_as_float(h << 16);
    const float h1 = __uint_as_float(h & 0xFFFF0000u);
    uint32_t l;
    asm("cvt.rn.bf16x2.f32 %0, %1, %2;" : "=r"(l) : "f"(x1 - h1), "f"(x0 - h0));
    hi = h; lo = l;
}
__device__ __forceinline__ void mma16(float* d, const uint32_t* a, uint32_t b0, uint32_t b1) {
    asm volatile("mma.sync.aligned.m16n8k16.row.col.f32.bf16.bf16.f32 "
        "{%0,%1,%2,%3}, {%4,%5,%6,%7}, {%8,%9}, {%0,%1,%2,%3};"
        : "+f"(d[0]), "+f"(d[1]), "+f"(d[2]), "+f"(d[3])
        : "r"(a[0]), "r"(a[1]), "r"(a[2]), "r"(a[3]), "r"(b0), "r"(b1));
}

// A-frag layout, BM=64: [split][kb][wb(4)][lane][reg]  (2048 words)
#define AFI3(s,kb,wb,l,r) (((((s)*2+(kb))*4+(wb))*32+(l))*4+(r))
// B-frag layout, n128: [split][kb][lane][idx 0..31], stride 36 (4608 words)
#define BFI2(s,kb,l,i)    ((((s)*2+(kb))*32+(l))*36+(i))

// ---------------------------------------------------------------------------
// prep: split x into hi/lo planes (one time)
// ---------------------------------------------------------------------------
__global__ __launch_bounds__(256) void splitx_kernel(const float* __restrict__ src) {
    const size_t i = ((size_t)blockIdx.x * 256 + threadIdx.x) * 4;
    const float4 v = *(const float4*)&src[i];
    uint32_t h0, l0, h1, l1;
    split_pair(v.x, v.y, h0, l0);
    split_pair(v.z, v.w, h1, l1);
    *(uint2*)&XH[i] = make_uint2(h0, h1);
    *(uint2*)&XL[i] = make_uint2(l0, l1);
}

// staging helpers (BM=64, BK=32)
__device__ __forceinline__ void storeA_64(uint32_t* smA,
    uint4 ph, uint4 pl, int c8, int wb, int ag, int arh)
{
    const uint32_t uh[4] = {ph.x, ph.y, ph.z, ph.w};
    const uint32_t ul[4] = {pl.x, pl.y, pl.z, pl.w};
    #pragma unroll
    for (int p = 0; p < 4; p++) {
        const int kk = c8 + 2*p;
        const int kb = kk >> 4, ccl = kk & 15;
        const int reg = arh + 2*(ccl >> 3);
        const int ln  = ag*4 + ((ccl & 7) >> 1);
        smA[AFI3(0,kb,wb,ln,reg)] = uh[p];
        smA[AFI3(1,kb,wb,ln,reg)] = ul[p];
    }
}
__device__ __forceinline__ void storeB_64(uint32_t* smB,
    const float4* wv, int n8, int kbB, int regB, int tB)
{
    const float* w0 = (const float*)&wv[0];
    const float* w1 = (const float*)&wv[2];
    #pragma unroll
    for (int j = 0; j < 8; j++) {
        const int n = n8 + j, gn = n & 7, nt = n >> 3;
        uint32_t hh, ll;
        split_pair(w0[j], w1[j], hh, ll);
        smB[BFI2(0,kbB, gn*4+tB, nt*2+regB)] = hh;
        smB[BFI2(1,kbB, gn*4+tB, nt*2+regB)] = ll;
    }
}

// ---------------------------------------------------------------------------
// GEMM mainloop: C[m64 x n128] = Asplit[m64 x 1024] @ B[1024 x n128], BK=32.
// 256 thr, 8 warps (m-strip x n-half). 2 blocks/SM. (R13-verbatim skeleton.)
// ---------------------------------------------------------------------------
#define GEMM_BODY3(A_H, A_L, BROW_STRIDE, WSRC)                                     \
    __shared__ uint32_t smA[2048];                                                  \
    __shared__ uint32_t smB[4608];                                                  \
    const int tid  = threadIdx.x;                                                   \
    const int lane = tid & 31, warp = tid >> 5;                                     \
    const int arow = tid >> 2, c8 = (tid & 3) * 8;                                  \
    const int awb = arow >> 4, ag = arow & 7, arh = (arow >> 3) & 1;                \
    const int kp = tid >> 4, n8 = (tid & 15) * 8;                                   \
    const int kbB = kp >> 3, regB = (kp >> 2) & 1, tB = kp & 3;                     \
    const int wms = warp >> 1, wnh = warp & 1;                                      \
    const uint32_t* xh = (const uint32_t*)(A_H) + c8/2;                             \
    const uint32_t* xl = (const uint32_t*)(A_L) + c8/2;                             \
    float acc[8][4] = {};                                                           \
    uint4 pah, pal;                                                                 \
    float4 wv[4];                                                                   \
    pah = *(const uint4*)&xh[0];                                                    \
    pal = *(const uint4*)&xl[0];                                                    \
    {   const float* wr = WSRC + (size_t)(2*kp) * (BROW_STRIDE);                    \
        wv[0] = *(const float4*)&wr[0];  wv[1] = *(const float4*)&wr[4];            \
        wr += (BROW_STRIDE);                                                        \
        wv[2] = *(const float4*)&wr[0];  wv[3] = *(const float4*)&wr[4]; }          \
    storeA_64(smA, pah, pal, c8, awb, ag, arh);                                     \
    storeB_64(smB, wv, n8, kbB, regB, tB);                                          \
    __syncthreads();                                                                \
    for (int it = 0; it < 32; it++) {                                               \
        const bool more = (it + 1 < 32);                                            \
        if (more) {                                                                 \
            pah = *(const uint4*)&xh[(it+1)*16];                                    \
            pal = *(const uint4*)&xl[(it+1)*16];                                    \
            const float* wr = WSRC + (size_t)((it+1)*32 + 2*kp) * (BROW_STRIDE);    \
            wv[0] = *(const float4*)&wr[0];  wv[1] = *(const float4*)&wr[4];        \
            wr += (BROW_STRIDE);                                                    \
            wv[2] = *(const float4*)&wr[0];  wv[3] = *(const float4*)&wr[4];        \
        }                                                                           \
        _Pragma("unroll")                                                           \
        for (int kb = 0; kb < 2; kb++) {                                            \
            uint32_t AH[4], AL[4];                                                  \
            *(uint4*)AH = *(const uint4*)&smA[AFI3(0,kb,wms,lane,0)];               \
            *(uint4*)AL = *(const uint4*)&smA[AFI3(1,kb,wms,lane,0)];               \
            _Pragma("unroll")                                                       \
            for (int q = 0; q < 4; q++) {                                           \
                const int bix = wnh*16 + 4*q;                                       \
                const uint4 h4 = *(const uint4*)&smB[BFI2(0,kb,lane,bix)];          \
                const uint4 l4 = *(const uint4*)&smB[BFI2(1,kb,lane,bix)];          \
                mma16(acc[2*q],   AH, h4.x, h4.y);                                  \
                mma16(acc[2*q+1], AH, h4.z, h4.w);                                  \
                mma16(acc[2*q],   AH, l4.x, l4.y);                                  \
                mma16(acc[2*q+1], AH, l4.z, l4.w);                                  \
                mma16(acc[2*q],   AL, h4.x, h4.y);                                  \
                mma16(acc[2*q+1], AL, h4.z, h4.w);                                  \
            }                                                                       \
        }                                                                           \
        __syncthreads();                                                            \
        if (more) {                                                                 \
            storeA_64(smA, pah, pal, c8, awb, ag, arh);                             \
            storeB_64(smB, wv, n8, kbB, regB, tB);                                  \
        }                                                                           \
        __syncthreads();                                                            \
    }

// ---------------------------------------------------------------------------
// Kernel 1: fused QKV projection. BM=64, 2 heads/block (n128).
// grid (64, 24), 256 thr.
// ---------------------------------------------------------------------------
__global__ __launch_bounds__(256) void qkv_kernel(
    const float* __restrict__ Wq, const float* __restrict__ Wk, const float* __restrict__ Wv,
    const float* __restrict__ bq, const float* __restrict__ bk, const float* __restrict__ bv)
{
    const int m0 = blockIdx.x * 64;
    const int which = blockIdx.y >> 3, hp = blockIdx.y & 7;
    const int h0 = 2*hp, h1 = 2*hp + 1;
    const float* Wb = (which == 0) ? Wq : (which == 1) ? Wk : Wv;
    const int n8_pre = (threadIdx.x & 15) * 8;
    const float* wsrc = Wb + (size_t)((n8_pre >= 64) ? h1 : h0) * DD * DHD + (n8_pre & 63);

    GEMM_BODY3(XH + (size_t)(m0 + (threadIdx.x>>2)) * DD,
               XL + (size_t)(m0 + (threadIdx.x>>2)) * DD,
               DHD, wsrc)

    // epilogue: bias, scale(q), split, store planes. warp covers one head.
    const float* biasb = (which == 0) ? bq : (which == 1) ? bk : bv;
    bf16* oh = (which == 0) ? QHg : (which == 1) ? KHg : VHg;
    bf16* ol = (which == 0) ? QLg : (which == 1) ? KLg : VLg;
    const float sc = (which == 0) ? 0.125f : 1.0f;
    const int head = wnh ? h1 : h0;

    const int g = lane >> 2, t4 = lane & 3;
    #pragma unroll
    for (int nt = 0; nt < 8; nt++) {
        const int n64 = nt*8 + 2*t4;
        const float b0 = biasb[head*DHD + n64], b1 = biasb[head*DHD + n64 + 1];
        uint32_t hi, lo;
        int m = m0 + wms*16 + g;
        size_t ridx = (((size_t)(m >> 11) * HH + head) * SS + (m & (SS-1))) * DHD + n64;
        split_pair((acc[nt][0] + b0) * sc, (acc[nt][1] + b1) * sc, hi, lo);
        *(uint32_t*)&oh[ridx] = hi; *(uint32_t*)&ol[ridx] = lo;
        m += 8;
        ridx = (((size_t)(m >> 11) * HH + head) * SS + (m & (SS-1))) * DHD + n64;
        split_pair((acc[nt][2] + b0) * sc, (acc[nt][3] + b1) * sc, hi, lo);
        *(uint32_t*)&oh[ridx] = hi; *(uint32_t*)&ol[ridx] = lo;
    }
}

// ---------------------------------------------------------------------------
// Kernel 3: output projection. BM=64, n128/block. grid (64, 8), 256 thr.
// ---------------------------------------------------------------------------
__global__ __launch_bounds__(256) void out_kernel(
    const float* __restrict__ Wo, const float* __restrict__ bo, float* __restrict__ out)
{
    const int m0 = blockIdx.x * 64;
    const int n0 = blockIdx.y * 128;
    const int n8_pre = (threadIdx.x & 15) * 8;
    const float* wsrc = Wo + n0 + n8_pre;

    GEMM_BODY3(XH + (size_t)(m0 + (threadIdx.x>>2)) * DD,
               XL + (size_t)(m0 + (threadIdx.x>>2)) * DD,
               DD, wsrc)

    const int g = lane >> 2, t4 = lane & 3;
    #pragma unroll
    for (int nt = 0; nt < 8; nt++) {
        const int n = n0 + wnh*64 + nt*8 + 2*t4;
        const float b0 = bo[n], b1 = bo[n+1];
        const int m_a = m0 + wms*16 + g, m_b = m_a + 8;
        *(float2*)&out[(size_t)m_a * DD + n] = make_float2(acc[nt][0] + b0, acc[nt][1] + b1);
        *(float2*)&out[(size_t)m_b * DD + n] = make_float2(acc[nt][2] + b0, acc[nt][3] + b1);
    }
}

// ---------------------------------------------------------------------------
// Kernel 2: flash attention (R9-verbatim structure; fast split only).
// grid (16, 16, 2), 256 thr, dyn smem 73728 B.
// ---------------------------------------------------------------------------
#define QFI(s,kb,wb,l,r) (((((s)*4+(kb))*8+(wb))*32+(l))*4+(r))   // 8192 words
#define KFI(s,kb,l,i)    ((((s)*4+(kb))*32+(l))*20+(i))           // 5120 words
#define ATT_SMEM_BYTES ((8192 + 5120 + 5120) * 4)

__global__ __launch_bounds__(256) void attn_kernel()
{
    extern __shared__ uint32_t sm[];
    uint32_t* QF = sm;
    uint32_t* KF = sm + 8192;
    uint32_t* VF = sm + 13312;

    const int tid  = threadIdx.x;
    const int lane = tid & 31, warp = tid >> 5;
    const int g = lane >> 2, t4 = lane & 3;
    const int q0 = blockIdx.x * 128;
    const int head = blockIdx.z * HH + blockIdx.y;
    const size_t hb = (size_t)head * SS;

    const int key = tid >> 2, kbK = tid & 3;
    const int gK = key & 7, ntK = key >> 3;
    const int kpV = tid >> 3, d8 = (tid & 7) * 8;
    const int kbV = kpV >> 3, regV = (kpV >> 2) & 1, tV = kpV & 3, ntV = tid & 7;

    const uint32_t* khw = (const uint32_t*)(KHg + (hb + key) * DHD) + kbK*8;
    const uint32_t* klw = (const uint32_t*)(KLg + (hb + key) * DHD) + kbK*8;
    const uint32_t* v0h = (const uint32_t*)(VHg + (hb + 2*kpV    ) * DHD) + d8/2;
    const uint32_t* v1h = (const uint32_t*)(VHg + (hb + 2*kpV + 1) * DHD) + d8/2;
    const uint32_t* v0l = (const uint32_t*)(VLg + (hb + 2*kpV    ) * DHD) + d8/2;
    const uint32_t* v1l = (const uint32_t*)(VLg + (hb + 2*kpV + 1) * DHD) + d8/2;
    const size_t krow = (size_t)64 * DHD / 2;

    uint32_t kuh[8], kul[8], va0[4], va1[4], vb0[4], vb1[4];

    {   // stage Q once
        const int r = tid >> 1, dseg = (tid & 1) * 32;
        const int wb = r >> 4, gg = r & 7, rh = (r >> 3) & 1;
        const uint32_t* qhw = (const uint32_t*)(QHg + (hb + q0 + r) * DHD) + dseg/2;
        const uint32_t* qlw = (const uint32_t*)(QLg + (hb + q0 + r) * DHD) + dseg/2;
        uint32_t uh[16], ul[16];
        #pragma unroll
        for (int c = 0; c < 4; c++) {
            *(uint4*)&uh[c*4] = *(const uint4*)&qhw[c*4];
            *(uint4*)&ul[c*4] = *(const uint4*)&qlw[c*4];
        }
        #pragma unroll
        for (int c4 = 0; c4 < 8; c4++) {
            const int d0 = dseg + c4*4;
            const int kb = d0 >> 4, cc = d0 & 15;
            const int reg = rh + 2*(cc >> 3), ln = gg*4 + ((cc & 7) >> 1);
            QF[QFI(0,kb,wb,ln,  reg)] = uh[c4*2];
            QF[QFI(0,kb,wb,ln+1,reg)] = uh[c4*2+1];
            QF[QFI(1,kb,wb,ln,  reg)] = ul[c4*2];
            QF[QFI(1,kb,wb,ln+1,reg)] = ul[c4*2+1];
        }
    }
    {   // stage KV tile 0
        *(uint4*)&kuh[0] = *(const uint4*)&khw[0];  *(uint4*)&kuh[4] = *(const uint4*)&khw[4];
        *(uint4*)&kul[0] = *(const uint4*)&klw[0];  *(uint4*)&kul[4] = *(const uint4*)&klw[4];
        *(uint4*)va0 = *(const uint4*)v0h;  *(uint4*)va1 = *(const uint4*)v1h;
        *(uint4*)vb0 = *(const uint4*)v0l;  *(uint4*)vb1 = *(const uint4*)v1l;
        #pragma unroll
        for (int c4 = 0; c4 < 4; c4++) {
            const int cc = c4*4, reg = cc >> 3, t0 = (cc & 7) >> 1;
            KF[KFI(0,kbK,gK*4+t0,  ntK*2+reg)] = kuh[c4*2];
            KF[KFI(0,kbK,gK*4+t0+1,ntK*2+reg)] = kuh[c4*2+1];
            KF[KFI(1,kbK,gK*4+t0,  ntK*2+reg)] = kul[c4*2];
            KF[KFI(1,kbK,gK*4+t0+1,ntK*2+reg)] = kul[c4*2+1];
        }
        #pragma unroll
        for (int j = 0; j < 8; j++) {
            const uint32_t sel = (j & 1) ? 0x7632u : 0x5410u;
            VF[KFI(0,kbV, j*4+tV, ntV*2+regV)] = __byte_perm(va0[j>>1], va1[j>>1], sel);
            VF[KFI(1,kbV, j*4+tV, ntV*2+regV)] = __byte_perm(vb0[j>>1], vb1[j>>1], sel);
        }
    }
    __syncthreads();

    float O[8][4] = {};
    float mx0 = -1e30f, mx1 = -1e30f, l0s = 0.f, l1s = 0.f;

    for (int kt = 0; kt < 32; kt++) {
        const bool more = (kt + 1 < 32);
        if (more) {
            const size_t off = (size_t)(kt+1) * krow;
            *(uint4*)&kuh[0] = *(const uint4*)&khw[off];  *(uint4*)&kuh[4] = *(const uint4*)&khw[off+4];
            *(uint4*)&kul[0] = *(const uint4*)&klw[off];  *(uint4*)&kul[4] = *(const uint4*)&klw[off+4];
            *(uint4*)va0 = *(const uint4*)&v0h[off];  *(uint4*)va1 = *(const uint4*)&v1h[off];
            *(uint4*)vb0 = *(const uint4*)&v0l[off];  *(uint4*)vb1 = *(const uint4*)&v1l[off];
        }

        float S[8][4] = {};
        #pragma unroll
        for (int kb = 0; kb < 4; kb++) {
            uint32_t QH[4], QL[4], kh[16], kl[16];
            *(uint4*)QH = *(const uint4*)&QF[QFI(0,kb,warp,lane,0)];
            *(uint4*)QL = *(const uint4*)&QF[QFI(1,kb,warp,lane,0)];
            #pragma unroll
            for (int q = 0; q < 4; q++) {
                *(uint4*)&kh[q*4] = *(const uint4*)&KF[KFI(0,kb,lane,q*4)];
                *(uint4*)&kl[q*4] = *(const uint4*)&KF[KFI(1,kb,lane,q*4)];
            }
            #pragma unroll
            for (int nt = 0; nt < 8; nt++) {
                mma16(S[nt], QH, kh[nt*2], kh[nt*2+1]);
                mma16(S[nt], QH, kl[nt*2], kl[nt*2+1]);
                mma16(S[nt], QL, kh[nt*2], kh[nt*2+1]);
            }
        }

        float mt0 = -1e30f, mt1 = -1e30f;
        #pragma unroll
        for (int nt = 0; nt < 8; nt++) {
            mt0 = fmaxf(mt0, fmaxf(S[nt][0], S[nt][1]));
            mt1 = fmaxf(mt1, fmaxf(S[nt][2], S[nt][3]));
        }
        #pragma unroll
        for (int off = 2; off >= 1; off >>= 1) {
            mt0 = fmaxf(mt0, __shfl_xor_sync(0xffffffffu, mt0, off));
            mt1 = fmaxf(mt1, __shfl_xor_sync(0xffffffffu, mt1, off));
        }
        const float mn0 = fmaxf(mx0, mt0), mn1 = fmaxf(mx1, mt1);
        const float c0 = __expf(mx0 - mn0), c1 = __expf(mx1 - mn1);
        float ls0 = 0.f, ls1 = 0.f;
        #pragma unroll
        for (int nt = 0; nt < 8; nt++) {
            S[nt][0] = __expf(S[nt][0] - mn0); ls0 += S[nt][0];
            S[nt][1] = __expf(S[nt][1] - mn0); ls0 += S[nt][1];
            S[nt][2] = __expf(S[nt][2] - mn1); ls1 += S[nt][2];
            S[nt][3] = __expf(S[nt][3] - mn1); ls1 += S[nt][3];
        }
        #pragma unroll
        for (int off = 2; off >= 1; off >>= 1) {
            ls0 += __shfl_xor_sync(0xffffffffu, ls0, off);
            ls1 += __shfl_xor_sync(0xffffffffu, ls1, off);
        }
        l0s = l0s * c0 + ls0;  l1s = l1s * c1 + ls1;
        mx0 = mn0;             mx1 = mn1;
        #pragma unroll
        for (int nt = 0; nt < 8; nt++) {
            O[nt][0] *= c0; O[nt][1] *= c0;
            O[nt][2] *= c1; O[nt][3] *= c1;
        }

        #pragma unroll
        for (int kb = 0; kb < 4; kb++) {
            uint32_t ph[4], pl[4], vh[16], vl[16];
            split_pair(S[2*kb  ][0], S[2*kb  ][1], ph[0], pl[0]);
            split_pair(S[2*kb  ][2], S[2*kb  ][3], ph[1], pl[1]);
            split_pair(S[2*kb+1][0], S[2*kb+1][1], ph[2], pl[2]);
            split_pair(S[2*kb+1][2], S[2*kb+1][3], ph[3], pl[3]);
            #pragma unroll
            for (int q = 0; q < 4; q++) {
                *(uint4*)&vh[q*4] = *(const uint4*)&VF[KFI(0,kb,lane,q*4)];
                *(uint4*)&vl[q*4] = *(const uint4*)&VF[KFI(1,kb,lane,q*4)];
            }
            #pragma unroll
            for (int nt = 0; nt < 8; nt++) {
                mma16(O[nt], ph, vh[nt*2], vh[nt*2+1]);
                mma16(O[nt], ph, vl[nt*2], vl[nt*2+1]);
                mma16(O[nt], pl, vh[nt*2], vh[nt*2+1]);
            }
        }
        __syncthreads();
        if (more) {
            #pragma unroll
            for (int c4 = 0; c4 < 4; c4++) {
                const int cc = c4*4, reg = cc >> 3, t0 = (cc & 7) >> 1;
                KF[KFI(0,kbK,gK*4+t0,  ntK*2+reg)] = kuh[c4*2];
                KF[KFI(0,kbK,gK*4+t0+1,ntK*2+reg)] = kuh[c4*2+1];
                KF[KFI(1,kbK,gK*4+t0,  ntK*2+reg)] = kul[c4*2];
                KF[KFI(1,kbK,gK*4+t0+1,ntK*2+reg)] = kul[c4*2+1];
            }
            #pragma unroll
            for (int j = 0; j < 8; j++) {
                const uint32_t sel = (j & 1) ? 0x7632u : 0x5410u;
                VF[KFI(0,kbV, j*4+tV, ntV*2+regV)] = __byte_perm(va0[j>>1], va1[j>>1], sel);
                VF[KFI(1,kbV, j*4+tV, ntV*2+regV)] = __byte_perm(vb0[j>>1], vb1[j>>1], sel);
            }
        }
        __syncthreads();
    }

    const float i0 = 1.f / l0s, i1 = 1.f / l1s;
    #pragma unroll
    for (int nt = 0; nt < 8; nt++) {
        const int n = nt*8 + 2*t4;
        const int sa = q0 + warp*16 + g, sb = sa + 8;
        const size_t ia = ((size_t)blockIdx.z * SS + sa) * DD + blockIdx.y * DHD + n;
        const size_t ib = ((size_t)blockIdx.z * SS + sb) * DD + blockIdx.y * DHD + n;
        uint32_t hi, lo;
        split_pair(O[nt][0]*i0, O[nt][1]*i0, hi, lo);
        *(uint32_t*)&XH[ia] = hi; *(uint32_t*)&XL[ia] = lo;
        split_pair(O[nt][2]*i1, O[nt][3]*i1, hi, lo);
        *(uint32_t*)&XH[ib] = hi; *(uint32_t*)&XL[ib] = lo;
    }
}

// ---------------------------------------------------------------------------
extern "C" void kernel_launch(void* const* d_in, const int* in_sizes, int n_in,
                              void* d_out, int out_size)
{
    (void)in_sizes; (void)n_in; (void)out_size;
    const float* x  = (const float*)d_in[0];
    const float* Wq = (const float*)d_in[1];
    const float* Wk = (const float*)d_in[2];
    const float* Wv = (const float*)d_in[3];
    const float* bq = (const float*)d_in[4];
    const float* bk = (const float*)d_in[5];
    const float* bv = (const float*)d_in[6];
    const float* Wo = (const float*)d_in[7];
    const float* bo = (const float*)d_in[8];
    float* out = (float*)d_out;

    (void)cudaFuncSetAttribute(attn_kernel, cudaFuncAttributeMaxDynamicSharedMemorySize,
                               ATT_SMEM_BYTES);

    splitx_kernel<<<(MM*DD)/1024, 256>>>(x);
    qkv_kernel<<<dim3(MM/64, 24), 256>>>(Wq, Wk, Wv, bq, bk, bv);
    attn_kernel<<<dim3(SS/128, HH, BB), 256, ATT_SMEM_BYTES>>>();
    out_kernel<<<dim3(MM/64, DD/128), 256>>>(Wo, bo, out);
}